// round 2
// baseline (speedup 1.0000x reference)
#include <cuda_runtime.h>
#include <math.h>

#define NNODE 50000
#define DD 256
#define HH 4
#define DZZ 64
#define RRR 4
#define KMEM 32
#define MMOT 2
#define NEDGE 1600000
#define NTRI 100000
#define PDIM 2816
#define OQ2 0
#define OK2 256
#define OQ3 512
#define OK3 1536
#define OQM 2560
#define C_LAM2 1.0f
#define C_LAM3 0.5f
#define C_LAMM 1.0f
#define C_BETA2 1.0f
#define C_BETA3 1.0f
#define C_BETAM 1.0f
#define C_GCLIP 1.0f
#define C_SCLIP 10.0f
#define C_DAMP 0.9999f
#define C_EPS 1e-5f

// ------------------- scratch (static device globals; no allocs) -------------
__device__ float g_G[(size_t)NNODE * DD];
__device__ float g_xhat[(size_t)NNODE * DD];
__device__ float g_rstd[NNODE];
__device__ float g_P[(size_t)NNODE * PDIM];    // packed projections [n][2816]
__device__ float g_dP[(size_t)NNODE * PDIM];   // packed projection grads
__device__ float g_dG[(size_t)NNODE * DD];
__device__ float g_Z2[NNODE * HH];
__device__ float g_Z3[NNODE * HH];
__device__ float g_Wcat[PDIM * DD];            // packed weights [p][d]
__device__ float g_Km[HH * DZZ * KMEM];        // memory keys [h][z][k]
__device__ double g_E;

// ------------------- helpers ------------------------------------------------
__device__ __forceinline__ float blk_sum256(float v) {
    __shared__ float red[8];
    #pragma unroll
    for (int o = 16; o; o >>= 1) v += __shfl_xor_sync(0xffffffffu, v, o);
    if ((threadIdx.x & 31) == 0) red[threadIdx.x >> 5] = v;
    __syncthreads();
    float r;
    if (threadIdx.x < 32) {
        float t = (threadIdx.x < 8) ? red[threadIdx.x] : 0.0f;
        #pragma unroll
        for (int o = 4; o; o >>= 1) t += __shfl_xor_sync(0xffffffffu, t, o);
        if (threadIdx.x == 0) red[0] = t;
    }
    __syncthreads();
    r = red[0];
    __syncthreads();
    return r;
}

// ------------------- zero kernels -------------------------------------------
__global__ void zero_dP_kernel() {
    size_t i = (size_t)blockIdx.x * blockDim.x + threadIdx.x;
    size_t n4 = (size_t)NNODE * PDIM / 4;
    float4 z = make_float4(0.f, 0.f, 0.f, 0.f);
    for (; i < n4; i += (size_t)gridDim.x * blockDim.x)
        ((float4*)g_dP)[i] = z;
}

__global__ void zero_small_kernel() {
    int i = blockIdx.x * blockDim.x + threadIdx.x;
    if (i < NNODE * HH) { g_Z2[i] = 0.f; g_Z3[i] = 0.f; }
    if (i == 0) g_E = 0.0;
}

// ------------------- LayerNorm forward --------------------------------------
__global__ void ln_fwd_kernel(const float* __restrict__ X,
                              const float* __restrict__ gamma,
                              const float* __restrict__ bias) {
    int n = blockIdx.x, d = threadIdx.x;
    size_t o = (size_t)n * DD + d;
    float x = X[o];
    float mu = blk_sum256(x) * (1.0f / DD);
    float dv = x - mu;
    float var = blk_sum256(dv * dv) * (1.0f / DD);
    float rstd = rsqrtf(var + C_EPS);
    float xh = dv * rstd;
    g_xhat[o] = xh;
    g_G[o] = gamma[d] * xh + bias[d];
    if (d == 0) g_rstd[n] = rstd;
}

// ------------------- weight packing -----------------------------------------
__global__ void pack_w_kernel(const float* __restrict__ wq2, const float* __restrict__ wk2,
                              const float* __restrict__ wq3, const float* __restrict__ wk3,
                              const float* __restrict__ wqm) {
    int i = blockIdx.x * blockDim.x + threadIdx.x;
    if (i >= PDIM * DD) return;
    int p = i / DD;
    float v;
    if (p < 256)       v = wq2[i];
    else if (p < 512)  v = wk2[i - 256 * DD];
    else if (p < 1536) v = wq3[i - 512 * DD];
    else if (p < 2560) v = wk3[i - 1536 * DD];
    else               v = wqm[i - 2560 * DD];
    g_Wcat[i] = v;
}

// Km[h][z][k] = sum_d B_mem[k,d] * W_Km[h,z,d]
__global__ void km_kernel(const float* __restrict__ Bm, const float* __restrict__ Wkm) {
    int i = blockIdx.x * blockDim.x + threadIdx.x;
    if (i >= HH * DZZ * KMEM) return;
    int k = i % KMEM;
    int hz = i / KMEM;
    const float* b = Bm + (size_t)k * DD;
    const float* w = Wkm + (size_t)hz * DD;
    float acc = 0.f;
    #pragma unroll 8
    for (int d = 0; d < DD; d++) acc += b[d] * w[d];
    g_Km[i] = acc;
}

// ------------------- GEMM forward: P[N,2816] = G[N,256] * Wcat[2816,256]^T --
__global__ void gemm_fwd_kernel() {
    __shared__ float As[16][128];
    __shared__ float Bs[16][128];
    const int m0 = blockIdx.y * 128;
    const int n0 = blockIdx.x * 128;
    const int tid = threadIdx.x;
    const int tn = tid & 15, tm = tid >> 4;
    float acc[8][8] = {};
    for (int k0 = 0; k0 < DD; k0 += 16) {
        #pragma unroll
        for (int L = 0; L < 2; L++) {
            int id = tid * 2 + L;
            int row = id >> 2;
            int kk = (id & 3) * 4;
            int gr = m0 + row;
            float4 v = make_float4(0.f, 0.f, 0.f, 0.f);
            if (gr < NNODE) v = *(const float4*)(g_G + (size_t)gr * DD + k0 + kk);
            As[kk + 0][row] = v.x; As[kk + 1][row] = v.y;
            As[kk + 2][row] = v.z; As[kk + 3][row] = v.w;
        }
        #pragma unroll
        for (int L = 0; L < 2; L++) {
            int id = tid * 2 + L;
            int row = id >> 2;
            int kk = (id & 3) * 4;
            float4 v = *(const float4*)(g_Wcat + (size_t)(n0 + row) * DD + k0 + kk);
            Bs[kk + 0][row] = v.x; Bs[kk + 1][row] = v.y;
            Bs[kk + 2][row] = v.z; Bs[kk + 3][row] = v.w;
        }
        __syncthreads();
        #pragma unroll
        for (int k = 0; k < 16; k++) {
            float a[8], b[8];
            *(float4*)(a) = *(const float4*)&As[k][tm * 8];
            *(float4*)(a + 4) = *(const float4*)&As[k][tm * 8 + 4];
            *(float4*)(b) = *(const float4*)&Bs[k][tn * 8];
            *(float4*)(b + 4) = *(const float4*)&Bs[k][tn * 8 + 4];
            #pragma unroll
            for (int i = 0; i < 8; i++)
                #pragma unroll
                for (int j = 0; j < 8; j++)
                    acc[i][j] += a[i] * b[j];
        }
        __syncthreads();
    }
    #pragma unroll
    for (int i = 0; i < 8; i++) {
        int gm = m0 + tm * 8 + i;
        if (gm >= NNODE) continue;
        #pragma unroll
        for (int j = 0; j < 8; j++)
            g_P[(size_t)gm * PDIM + n0 + tn * 8 + j] = acc[i][j];
    }
}

// ------------------- GEMM backward: dG[N,256] = dP[N,2816] * Wcat[2816,256] -
__global__ void gemm_bwd_kernel() {
    __shared__ float As[16][128];
    __shared__ float Bs[16][128];
    const int m0 = blockIdx.y * 128;
    const int n0 = blockIdx.x * 128;
    const int tid = threadIdx.x;
    const int tn = tid & 15, tm = tid >> 4;
    float acc[8][8] = {};
    for (int k0 = 0; k0 < PDIM; k0 += 16) {
        #pragma unroll
        for (int L = 0; L < 2; L++) {
            int id = tid * 2 + L;
            int row = id >> 2;
            int kk = (id & 3) * 4;
            int gr = m0 + row;
            float4 v = make_float4(0.f, 0.f, 0.f, 0.f);
            if (gr < NNODE) v = *(const float4*)(g_dP + (size_t)gr * PDIM + k0 + kk);
            As[kk + 0][row] = v.x; As[kk + 1][row] = v.y;
            As[kk + 2][row] = v.z; As[kk + 3][row] = v.w;
        }
        #pragma unroll
        for (int L = 0; L < 2; L++) {
            int id = tid * 2 + L;
            int krow = id >> 5;          // 0..15
            int nn = (id & 31) * 4;      // 0..124
            float4 v = *(const float4*)(g_Wcat + (size_t)(k0 + krow) * DD + n0 + nn);
            *(float4*)&Bs[krow][nn] = v;
        }
        __syncthreads();
        #pragma unroll
        for (int k = 0; k < 16; k++) {
            float a[8], b[8];
            *(float4*)(a) = *(const float4*)&As[k][tm * 8];
            *(float4*)(a + 4) = *(const float4*)&As[k][tm * 8 + 4];
            *(float4*)(b) = *(const float4*)&Bs[k][tn * 8];
            *(float4*)(b + 4) = *(const float4*)&Bs[k][tn * 8 + 4];
            #pragma unroll
            for (int i = 0; i < 8; i++)
                #pragma unroll
                for (int j = 0; j < 8; j++)
                    acc[i][j] += a[i] * b[j];
        }
        __syncthreads();
    }
    #pragma unroll
    for (int i = 0; i < 8; i++) {
        int gm = m0 + tm * 8 + i;
        if (gm >= NNODE) continue;
        #pragma unroll
        for (int j = 0; j < 8; j++)
            g_dG[(size_t)gm * DD + n0 + tn * 8 + j] = acc[i][j];
    }
}

// ------------------- pair (2nd-order) edges ---------------------------------
// warp per edge; 4 heads x 8 lanes; each lane handles 8 of 64 z-dims.
__device__ __forceinline__ float e2_dot(int c, int u, int h, int sub,
                                        float4& qa, float4& qb, float4& ka, float4& kb) {
    const float* q = g_P + (size_t)c * PDIM + OQ2 + h * DZZ + sub * 8;
    const float* kk = g_P + (size_t)u * PDIM + OK2 + h * DZZ + sub * 8;
    qa = *(const float4*)q;  qb = *(const float4*)(q + 4);
    ka = *(const float4*)kk; kb = *(const float4*)(kk + 4);
    float s = qa.x * ka.x + qa.y * ka.y + qa.z * ka.z + qa.w * ka.w
            + qb.x * kb.x + qb.y * kb.y + qb.z * kb.z + qb.w * kb.w;
    s += __shfl_xor_sync(0xffffffffu, s, 1);
    s += __shfl_xor_sync(0xffffffffu, s, 2);
    s += __shfl_xor_sync(0xffffffffu, s, 4);
    return s * C_BETA2;
}

__global__ void e2_fwd_kernel(const int* __restrict__ c2, const int* __restrict__ u2) {
    int e = blockIdx.x * 8 + (threadIdx.x >> 5);
    if (e >= NEDGE) return;
    int lane = threadIdx.x & 31;
    int h = lane >> 3, sub = lane & 7;
    int c = c2[e], u = u2[e];
    float4 qa, qb, ka, kb;
    float s = e2_dot(c, u, h, sub, qa, qb, ka, kb);
    if (sub == 0) atomicAdd(&g_Z2[c * HH + h], expf(s));
}

__global__ void e2_bwd_kernel(const int* __restrict__ c2, const int* __restrict__ u2) {
    int e = blockIdx.x * 8 + (threadIdx.x >> 5);
    if (e >= NEDGE) return;
    int lane = threadIdx.x & 31;
    int h = lane >> 3, sub = lane & 7;
    int c = c2[e], u = u2[e];
    float4 qa, qb, ka, kb;
    float s = e2_dot(c, u, h, sub, qa, qb, ka, kb);
    float z = g_Z2[c * HH + h];
    float w = -C_LAM2 * expf(s) / z;
    float* dq = g_dP + (size_t)c * PDIM + OQ2 + h * DZZ + sub * 8;
    float* dk = g_dP + (size_t)u * PDIM + OK2 + h * DZZ + sub * 8;
    atomicAdd(dq + 0, w * ka.x); atomicAdd(dq + 1, w * ka.y);
    atomicAdd(dq + 2, w * ka.z); atomicAdd(dq + 3, w * ka.w);
    atomicAdd(dq + 4, w * kb.x); atomicAdd(dq + 5, w * kb.y);
    atomicAdd(dq + 6, w * kb.z); atomicAdd(dq + 7, w * kb.w);
    atomicAdd(dk + 0, w * qa.x); atomicAdd(dk + 1, w * qa.y);
    atomicAdd(dk + 2, w * qa.z); atomicAdd(dk + 3, w * qa.w);
    atomicAdd(dk + 4, w * qb.x); atomicAdd(dk + 5, w * qb.y);
    atomicAdd(dk + 6, w * qb.z); atomicAdd(dk + 7, w * qb.w);
}

// ------------------- triple (3rd-order) motifs -------------------------------
// warp per triple; 4 heads x 8 lanes; each lane 32 of 256 (r,z) positions.
__device__ __forceinline__ float e3_score(const float* __restrict__ T,
                                          int c, int u, int v, int m, int h, int sub) {
    size_t qb = (size_t)c * PDIM + OQ3 + h * 256 + sub * 32;
    size_t ub = (size_t)u * PDIM + OK3 + h * 256 + sub * 32;
    size_t vb = (size_t)v * PDIM + OK3 + h * 256 + sub * 32;
    const float* Tb = T + (size_t)m * (HH * RRR * DZZ) + h * 256 + sub * 32;
    float s = 0.f;
    #pragma unroll
    for (int j = 0; j < 32; j += 4) {
        float4 q = *(const float4*)(g_P + qb + j);
        float4 a = *(const float4*)(g_P + ub + j);
        float4 b = *(const float4*)(g_P + vb + j);
        float4 t = *(const float4*)(Tb + j);
        s += q.x * a.x * b.x * t.x + q.y * a.y * b.y * t.y
           + q.z * a.z * b.z * t.z + q.w * a.w * b.w * t.w;
    }
    s += __shfl_xor_sync(0xffffffffu, s, 1);
    s += __shfl_xor_sync(0xffffffffu, s, 2);
    s += __shfl_xor_sync(0xffffffffu, s, 4);
    return s * C_BETA3;
}

__global__ void e3_fwd_kernel(const int* __restrict__ c3, const int* __restrict__ u3,
                              const int* __restrict__ v3, const int* __restrict__ tt,
                              const float* __restrict__ T) {
    int t = blockIdx.x * 8 + (threadIdx.x >> 5);
    if (t >= NTRI) return;
    int lane = threadIdx.x & 31;
    int h = lane >> 3, sub = lane & 7;
    int c = c3[t], u = u3[t], v = v3[t], m = tt[t];
    float s = e3_score(T, c, u, v, m, h, sub);
    if (sub == 0) atomicAdd(&g_Z3[c * HH + h], expf(s));
}

__global__ void e3_bwd_kernel(const int* __restrict__ c3, const int* __restrict__ u3,
                              const int* __restrict__ v3, const int* __restrict__ tt,
                              const float* __restrict__ T) {
    int t = blockIdx.x * 8 + (threadIdx.x >> 5);
    if (t >= NTRI) return;
    int lane = threadIdx.x & 31;
    int h = lane >> 3, sub = lane & 7;
    int c = c3[t], u = u3[t], v = v3[t], m = tt[t];
    float s = e3_score(T, c, u, v, m, h, sub);
    float z = g_Z3[c * HH + h];
    float w = -C_LAM3 * expf(s) / z;
    size_t qb = (size_t)c * PDIM + OQ3 + h * 256 + sub * 32;
    size_t ub = (size_t)u * PDIM + OK3 + h * 256 + sub * 32;
    size_t vb = (size_t)v * PDIM + OK3 + h * 256 + sub * 32;
    const float* Tb = T + (size_t)m * (HH * RRR * DZZ) + h * 256 + sub * 32;
    #pragma unroll
    for (int j = 0; j < 32; j += 4) {
        float4 q = *(const float4*)(g_P + qb + j);
        float4 a = *(const float4*)(g_P + ub + j);
        float4 b = *(const float4*)(g_P + vb + j);
        float4 tv = *(const float4*)(Tb + j);
        atomicAdd(g_dP + qb + j + 0, w * a.x * b.x * tv.x);
        atomicAdd(g_dP + qb + j + 1, w * a.y * b.y * tv.y);
        atomicAdd(g_dP + qb + j + 2, w * a.z * b.z * tv.z);
        atomicAdd(g_dP + qb + j + 3, w * a.w * b.w * tv.w);
        atomicAdd(g_dP + ub + j + 0, w * q.x * b.x * tv.x);
        atomicAdd(g_dP + ub + j + 1, w * q.y * b.y * tv.y);
        atomicAdd(g_dP + ub + j + 2, w * q.z * b.z * tv.z);
        atomicAdd(g_dP + ub + j + 3, w * q.w * b.w * tv.w);
        atomicAdd(g_dP + vb + j + 0, w * q.x * a.x * tv.x);
        atomicAdd(g_dP + vb + j + 1, w * q.y * a.y * tv.y);
        atomicAdd(g_dP + vb + j + 2, w * q.z * a.z * tv.z);
        atomicAdd(g_dP + vb + j + 3, w * q.w * a.w * tv.w);
    }
}

// ------------------- memory term (fused fwd + bwd, no atomics on dP) --------
__global__ void mem_kernel() {
    __shared__ float Ks[HH * DZZ * 33];
    __shared__ double eacc[8];
    for (int i = threadIdx.x; i < HH * DZZ * KMEM; i += 256) {
        int k = i & 31;
        int hz = i >> 5;
        Ks[hz * 33 + k] = g_Km[i];
    }
    __syncthreads();
    int w = threadIdx.x >> 5, lane = threadIdx.x & 31;
    int n = blockIdx.x * 8 + w;
    double lsum = 0.0;
    if (n < NNODE) {
        for (int h = 0; h < HH; h++) {
            size_t qoff = (size_t)n * PDIM + OQM + h * DZZ;
            float q0 = g_P[qoff + 2 * lane];
            float q1 = g_P[qoff + 2 * lane + 1];
            float acc = 0.f;
            #pragma unroll
            for (int zi = 0; zi < 32; zi++) {
                float qa = __shfl_sync(0xffffffffu, q0, zi);
                float qb = __shfl_sync(0xffffffffu, q1, zi);
                acc += qa * Ks[(h * DZZ + 2 * zi) * 33 + lane]
                     + qb * Ks[(h * DZZ + 2 * zi + 1) * 33 + lane];
            }
            float sm = C_BETAM * acc;  // score for k = lane
            float mx = sm;
            #pragma unroll
            for (int o = 16; o; o >>= 1) mx = fmaxf(mx, __shfl_xor_sync(0xffffffffu, mx, o));
            float ex = expf(sm - mx);
            float ssum = ex;
            #pragma unroll
            for (int o = 16; o; o >>= 1) ssum += __shfl_xor_sync(0xffffffffu, ssum, o);
            float lse = mx + logf(ssum);
            float p = ex / ssum;
            lsum += (double)lse;
            float d0 = 0.f, d1 = 0.f;
            #pragma unroll
            for (int k = 0; k < 32; k++) {
                float pk = __shfl_sync(0xffffffffu, p, k);
                d0 += pk * Ks[(h * DZZ + 2 * lane) * 33 + k];
                d1 += pk * Ks[(h * DZZ + 2 * lane + 1) * 33 + k];
            }
            g_dP[qoff + 2 * lane] = -C_LAMM * d0;
            g_dP[qoff + 2 * lane + 1] = -C_LAMM * d1;
        }
    }
    if (lane == 0) eacc[w] = -(double)C_LAMM * lsum;
    __syncthreads();
    if (threadIdx.x == 0) {
        double tot = 0.0;
        for (int i = 0; i < 8; i++) tot += eacc[i];
        atomicAdd(&g_E, tot);
    }
}

// ------------------- energy from segment sums --------------------------------
__global__ void lse_sum_kernel() {
    int i = blockIdx.x * 256 + threadIdx.x;
    double v = 0.0;
    if (i < NNODE * HH) {
        float z2 = g_Z2[i];
        if (z2 > 0.f) v -= (double)(C_LAM2 / C_BETA2) * (double)logf(z2);
        float z3 = g_Z3[i];
        if (z3 > 0.f) v -= (double)(C_LAM3 / C_BETA3) * (double)logf(z3);
    }
    #pragma unroll
    for (int o = 16; o; o >>= 1) v += __shfl_xor_sync(0xffffffffu, v, o);
    __shared__ double rd[8];
    if ((threadIdx.x & 31) == 0) rd[threadIdx.x >> 5] = v;
    __syncthreads();
    if (threadIdx.x == 0) {
        double t = 0.0;
        for (int j = 0; j < 8; j++) t += rd[j];
        atomicAdd(&g_E, t);
    }
}

// ------------------- LN backward + clip + step + clip (fused) ----------------
__global__ void ln_bwd_update_kernel(const float* __restrict__ X,
                                     const float* __restrict__ gamma,
                                     const float* __restrict__ step,
                                     float* __restrict__ out) {
    int n = blockIdx.x, d = threadIdx.x;
    size_t o = (size_t)n * DD + d;
    float dg = g_dG[o];
    float xh = g_xhat[o];
    float dxh = dg * gamma[d];
    float s1 = blk_sum256(dxh) * (1.0f / DD);
    float s2 = blk_sum256(dxh * xh) * (1.0f / DD);
    float dx = g_rstd[n] * (dxh - s1 - xh * s2);
    float gn2 = blk_sum256(dx * dx);
    float gn = sqrtf(gn2);
    float sc = C_GCLIP / fmaxf(gn, C_GCLIP);
    float xn = X[o] - step[0] * C_DAMP * dx * sc;
    float sn2 = blk_sum256(xn * xn);
    float sn = sqrtf(sn2);
    float sc2 = C_SCLIP / fmaxf(sn, C_SCLIP);
    out[o] = xn * sc2;
}

__global__ void finalize_kernel(float* __restrict__ out, int out_size) {
    if (out_size > NNODE * DD) out[(size_t)NNODE * DD] = (float)g_E;
}

// ------------------- launch --------------------------------------------------
extern "C" void kernel_launch(void* const* d_in, const int* in_sizes, int n_in,
                              void* d_out, int out_size) {
    const float* X     = (const float*)d_in[0];
    const int*   c2    = (const int*)d_in[1];
    const int*   u2    = (const int*)d_in[2];
    const int*   c3    = (const int*)d_in[3];
    const int*   u3    = (const int*)d_in[4];
    const int*   v3    = (const int*)d_in[5];
    const int*   tt    = (const int*)d_in[6];
    // d_in[7] = batch (unused)
    const float* step  = (const float*)d_in[8];
    const float* gamma = (const float*)d_in[9];
    const float* bias  = (const float*)d_in[10];
    const float* wq2   = (const float*)d_in[11];
    const float* wk2   = (const float*)d_in[12];
    const float* wq3   = (const float*)d_in[13];
    const float* wk3   = (const float*)d_in[14];
    const float* T     = (const float*)d_in[15];
    const float* wqm   = (const float*)d_in[16];
    const float* wkm   = (const float*)d_in[17];
    const float* bmem  = (const float*)d_in[18];
    float* out = (float*)d_out;

    zero_dP_kernel<<<4096, 256>>>();
    zero_small_kernel<<<(NNODE * HH + 255) / 256, 256>>>();
    ln_fwd_kernel<<<NNODE, 256>>>(X, gamma, bias);
    pack_w_kernel<<<(PDIM * DD + 255) / 256, 256>>>(wq2, wk2, wq3, wk3, wqm);
    km_kernel<<<(HH * DZZ * KMEM + 255) / 256, 256>>>(bmem, wkm);

    gemm_fwd_kernel<<<dim3(PDIM / 128, (NNODE + 127) / 128), 256>>>();

    e2_fwd_kernel<<<NEDGE / 8, 256>>>(c2, u2);
    e3_fwd_kernel<<<NTRI / 8, 256>>>(c3, u3, v3, tt, T);
    mem_kernel<<<(NNODE + 7) / 8, 256>>>();
    lse_sum_kernel<<<(NNODE * HH + 255) / 256, 256>>>();

    e2_bwd_kernel<<<NEDGE / 8, 256>>>(c2, u2);
    e3_bwd_kernel<<<NTRI / 8, 256>>>(c3, u3, v3, tt, T);

    gemm_bwd_kernel<<<dim3(DD / 128, (NNODE + 127) / 128), 256>>>();
    ln_bwd_update_kernel<<<NNODE, 256>>>(X, gamma, step, out);
    finalize_kernel<<<1, 1>>>(out, out_size);
}

// round 9
// speedup vs baseline: 1.3842x; 1.3842x over previous
#include <cuda_runtime.h>
#include <cuda_bf16.h>
#include <math.h>
#include <stdint.h>

#define NNODE 50000
#define NPAD 50048            // 391*128, padded row count for MMA tiles
#define DD 256
#define HH 4
#define DZZ 64
#define RRR 4
#define KMEM 32
#define MMOT 2
#define NEDGE 1600000
#define NTRI 100000
#define PDIM 2816
#define OQ2 0
#define OK2 256
#define OQ3 512
#define OK3 1536
#define OQM 2560
#define C_LAM2 1.0f
#define C_LAM3 0.5f
#define C_LAMM 1.0f
#define C_BETA2 1.0f
#define C_BETA3 1.0f
#define C_BETAM 1.0f
#define C_GCLIP 1.0f
#define C_SCLIP 10.0f
#define C_DAMP 0.9999f
#define C_EPS 1e-5f

// ------------------- scratch (static device globals; no allocs) -------------
__device__ float g_xhat[(size_t)NNODE * DD];
__device__ float g_rstd[NNODE];
__device__ float g_P[(size_t)NNODE * PDIM];    // packed projections [n][2816]
__device__ float g_dP[(size_t)NNODE * PDIM];   // packed projection grads
__device__ float g_dG[(size_t)NNODE * DD];
__device__ float g_Z2[NNODE * HH];
__device__ float g_Z3[NNODE * HH];
__device__ float g_Km[HH * DZZ * KMEM];        // memory keys [h][z][k]
__device__ double g_E;
// bf16 operands for HMMA GEMMs (padded rows stay zero-initialized)
__device__ __nv_bfloat16 g_Ghi[(size_t)NPAD * DD];
__device__ __nv_bfloat16 g_Glo[(size_t)NPAD * DD];
__device__ __nv_bfloat16 g_Whi[(size_t)PDIM * DD];
__device__ __nv_bfloat16 g_Wlo[(size_t)PDIM * DD];
__device__ __nv_bfloat16 g_WThi[(size_t)DD * PDIM];
__device__ __nv_bfloat16 g_dPhi[(size_t)NPAD * PDIM];

// ------------------- PTX helpers (plain sm_103-safe) -------------------------
__device__ __forceinline__ uint32_t smem_u32(const void* p) {
    uint32_t a;
    asm("{ .reg .u64 t; cvta.to.shared.u64 t, %1; cvt.u32.u64 %0, t; }"
        : "=r"(a) : "l"(p));
    return a;
}
__device__ __forceinline__ void cp16(uint32_t dst, const void* src) {
    asm volatile("cp.async.cg.shared.global [%0], [%1], 16;" :: "r"(dst), "l"(src));
}
#define CP_COMMIT() asm volatile("cp.async.commit_group;" ::: "memory")
#define CP_WAIT1()  asm volatile("cp.async.wait_group 1;" ::: "memory")
__device__ __forceinline__ void ldmx4(uint32_t* r, uint32_t addr) {
    asm volatile("ldmatrix.sync.aligned.m8n8.x4.shared.b16 {%0,%1,%2,%3}, [%4];"
                 : "=r"(r[0]), "=r"(r[1]), "=r"(r[2]), "=r"(r[3]) : "r"(addr));
}
__device__ __forceinline__ void mma16816(float* c, const uint32_t* a,
                                         uint32_t b0, uint32_t b1) {
    asm volatile("mma.sync.aligned.m16n8k16.row.col.f32.bf16.bf16.f32 "
                 "{%0,%1,%2,%3}, {%4,%5,%6,%7}, {%8,%9}, {%0,%1,%2,%3};"
                 : "+f"(c[0]), "+f"(c[1]), "+f"(c[2]), "+f"(c[3])
                 : "r"(a[0]), "r"(a[1]), "r"(a[2]), "r"(a[3]), "r"(b0), "r"(b1));
}
__device__ __forceinline__ uint32_t swz128(uint32_t b) { return b ^ ((b >> 3) & 0x70); }

// ------------------- block reduce helper ------------------------------------
__device__ __forceinline__ float blk_sum256(float v) {
    __shared__ float red[8];
    #pragma unroll
    for (int o = 16; o; o >>= 1) v += __shfl_xor_sync(0xffffffffu, v, o);
    if ((threadIdx.x & 31) == 0) red[threadIdx.x >> 5] = v;
    __syncthreads();
    float r;
    if (threadIdx.x < 32) {
        float t = (threadIdx.x < 8) ? red[threadIdx.x] : 0.0f;
        #pragma unroll
        for (int o = 4; o; o >>= 1) t += __shfl_xor_sync(0xffffffffu, t, o);
        if (threadIdx.x == 0) red[0] = t;
    }
    __syncthreads();
    r = red[0];
    __syncthreads();
    return r;
}

// ------------------- zero kernels -------------------------------------------
__global__ void zero_dP_kernel() {
    size_t i = (size_t)blockIdx.x * blockDim.x + threadIdx.x;
    size_t n4 = (size_t)NNODE * PDIM / 4;
    float4 z = make_float4(0.f, 0.f, 0.f, 0.f);
    for (; i < n4; i += (size_t)gridDim.x * blockDim.x)
        ((float4*)g_dP)[i] = z;
}
__global__ void zero_small_kernel() {
    int i = blockIdx.x * blockDim.x + threadIdx.x;
    if (i < NNODE * HH) { g_Z2[i] = 0.f; g_Z3[i] = 0.f; }
    if (i == 0) g_E = 0.0;
}

// ------------------- LayerNorm forward (+ bf16 hi/lo split of G) ------------
__global__ void ln_fwd_kernel(const float* __restrict__ X,
                              const float* __restrict__ gamma,
                              const float* __restrict__ bias) {
    int n = blockIdx.x, d = threadIdx.x;
    size_t o = (size_t)n * DD + d;
    float x = X[o];
    float mu = blk_sum256(x) * (1.0f / DD);
    float dv = x - mu;
    float var = blk_sum256(dv * dv) * (1.0f / DD);
    float rstd = rsqrtf(var + C_EPS);
    float xh = dv * rstd;
    g_xhat[o] = xh;
    float gv = gamma[d] * xh + bias[d];
    __nv_bfloat16 hi = __float2bfloat16(gv);
    g_Ghi[o] = hi;
    g_Glo[o] = __float2bfloat16(gv - __bfloat162float(hi));
    if (d == 0) g_rstd[n] = rstd;
}

// ------------------- weight packing (+ split + transpose) -------------------
__global__ void pack_w_kernel(const float* __restrict__ wq2, const float* __restrict__ wk2,
                              const float* __restrict__ wq3, const float* __restrict__ wk3,
                              const float* __restrict__ wqm) {
    int i = blockIdx.x * blockDim.x + threadIdx.x;
    if (i >= PDIM * DD) return;
    int p = i / DD, d = i % DD;
    float v;
    if (p < 256)       v = wq2[i];
    else if (p < 512)  v = wk2[i - 256 * DD];
    else if (p < 1536) v = wq3[i - 512 * DD];
    else if (p < 2560) v = wk3[i - 1536 * DD];
    else               v = wqm[i - 2560 * DD];
    __nv_bfloat16 hi = __float2bfloat16(v);
    g_Whi[i] = hi;
    g_Wlo[i] = __float2bfloat16(v - __bfloat162float(hi));
    g_WThi[(size_t)d * PDIM + p] = hi;
}

// Km[h][z][k] = sum_d B_mem[k,d] * W_Km[h,z,d]
__global__ void km_kernel(const float* __restrict__ Bm, const float* __restrict__ Wkm) {
    int i = blockIdx.x * blockDim.x + threadIdx.x;
    if (i >= HH * DZZ * KMEM) return;
    int k = i % KMEM;
    int hz = i / KMEM;
    const float* b = Bm + (size_t)k * DD;
    const float* w = Wkm + (size_t)hz * DD;
    float acc = 0.f;
    #pragma unroll 8
    for (int d = 0; d < DD; d++) acc += b[d] * w[d];
    g_Km[i] = acc;
}

// ------------------- convert dP to bf16 (hi only; bwd tolerates bf16) --------
__global__ void conv_dP_kernel() {
    size_t i = (size_t)blockIdx.x * blockDim.x + threadIdx.x;
    size_t n4 = (size_t)NNODE * PDIM / 4;
    __nv_bfloat162* ph = (__nv_bfloat162*)g_dPhi;
    for (; i < n4; i += (size_t)gridDim.x * blockDim.x) {
        float4 v = ((const float4*)g_dP)[i];
        ph[2 * i]     = __nv_bfloat162(__float2bfloat16(v.x), __float2bfloat16(v.y));
        ph[2 * i + 1] = __nv_bfloat162(__float2bfloat16(v.z), __float2bfloat16(v.w));
    }
}

// ------------------- HMMA GEMM (mma.sync bf16, cp.async pipelined) -----------
// C[M][N] = A[M][K] * B[N][K]^T  (both K-major)
// mode 0: P = G * Wcat^T. N-tiles 0-3 (Q2/K2 cols) use bf16x3 split
//         (12 chunks: hi*hi, hi*lo, lo*hi over K=256); other tiles 4 chunks hi*hi.
// mode 1: dG = dPhi * WThi^T-style (single bf16 pass, K=2816, 44 chunks).
#define TBM 128
#define TBN 128
#define TBK 64
#define TILEB 16384                    // one operand tile: 128 rows x 128B
#define STAGEB (2 * TILEB)
#define GSMEM (3 * STAGEB)             // 3 stages

__global__ __launch_bounds__(256, 1) void gemm_mma_kernel(int mode) {
    extern __shared__ char sm[];
    const uint32_t su = smem_u32(sm);
    const int tid = threadIdx.x, wid = tid >> 5, lane = tid & 31;
    const int m0 = blockIdx.y * TBM;
    const int n0 = blockIdx.x * TBN;
    const int wm = wid & 3, wn = wid >> 2;    // 4 M-warps x 2 N-warps

    int lda, ldb, ldc, nchunk;
    float* C;
    if (mode == 0) {
        lda = DD; ldb = DD; ldc = PDIM; C = g_P;
        nchunk = (n0 < 512) ? 12 : 4;
    } else {
        lda = PDIM; ldb = PDIM; ldc = DD; C = g_dG;
        nchunk = PDIM / TBK;              // 44
    }

    auto prefetch = [&](int c, int st) {
        const __nv_bfloat16 *Asrc, *Bsrc;
        int k0;
        if (mode == 0) {
            int pass = c >> 2;
            k0 = (c & 3) * TBK;
            Asrc = (pass < 2) ? g_Ghi : g_Glo;
            Bsrc = (pass == 1) ? g_Wlo : g_Whi;
        } else {
            k0 = c * TBK;
            Asrc = g_dPhi;
            Bsrc = g_WThi;
        }
        uint32_t bufA = su + st * STAGEB;
        uint32_t bufB = bufA + TILEB;
        #pragma unroll
        for (int g = 0; g < 4; g++) {
            int i = tid + g * 256;            // 0..1023
            int row = i >> 3;
            int c8 = (i & 7) * 8;
            uint32_t off = swz128((uint32_t)(row * 128 + (i & 7) * 16));
            cp16(bufA + off, Asrc + (size_t)(m0 + row) * lda + k0 + c8);
            cp16(bufB + off, Bsrc + (size_t)(n0 + row) * ldb + k0 + c8);
        }
    };

    float acc[2][8][4] = {};

    prefetch(0, 0); CP_COMMIT();
    prefetch(1, 1); CP_COMMIT();

    for (int c = 0; c < nchunk; c++) {
        const int st = c % 3;
        CP_WAIT1();
        __syncthreads();
        if (c + 2 < nchunk) prefetch(c + 2, (c + 2) % 3);
        CP_COMMIT();

        const uint32_t aBase = su + st * STAGEB;
        const uint32_t bBase = aBase + TILEB;
        #pragma unroll
        for (int kk = 0; kk < 4; kk++) {
            uint32_t ra[2][4];
            #pragma unroll
            for (int im = 0; im < 2; im++) {
                int r = wm * 32 + im * 16 + (lane & 15);
                uint32_t byte = (uint32_t)(r * 128 + kk * 32 + ((lane >> 4) * 16));
                ldmx4(ra[im], aBase + swz128(byte));
            }
            uint32_t rb[4][4];
            #pragma unroll
            for (int jb = 0; jb < 4; jb++) {
                int r = wn * 64 + jb * 16 + (lane & 7) + ((lane >> 4) * 8);
                uint32_t byte = (uint32_t)(r * 128 + kk * 32 + (((lane >> 3) & 1) * 16));
                ldmx4(rb[jb], bBase + swz128(byte));
            }
            #pragma unroll
            for (int im = 0; im < 2; im++)
                #pragma unroll
                for (int jb = 0; jb < 4; jb++) {
                    mma16816(acc[im][jb * 2],     ra[im], rb[jb][0], rb[jb][1]);
                    mma16816(acc[im][jb * 2 + 1], ra[im], rb[jb][2], rb[jb][3]);
                }
        }
    }

    // epilogue: C fragment lane layout: rows l/4 and l/4+8, cols (l%4)*2,+1
    #pragma unroll
    for (int im = 0; im < 2; im++)
        #pragma unroll
        for (int jn = 0; jn < 8; jn++) {
            float* cc = acc[im][jn];
            int m = m0 + wm * 32 + im * 16 + (lane >> 2);
            int col = n0 + wn * 64 + jn * 8 + (lane & 3) * 2;
            if (m < NNODE)
                *(float2*)(C + (size_t)m * ldc + col) = make_float2(cc[0], cc[1]);
            if (m + 8 < NNODE)
                *(float2*)(C + (size_t)(m + 8) * ldc + col) = make_float2(cc[2], cc[3]);
        }
}

// ------------------- pair (2nd-order) edges ---------------------------------
__device__ __forceinline__ float e2_dot(int c, int u, int h, int sub,
                                        float4& qa, float4& qb, float4& ka, float4& kb) {
    const float* q = g_P + (size_t)c * PDIM + OQ2 + h * DZZ + sub * 8;
    const float* kk = g_P + (size_t)u * PDIM + OK2 + h * DZZ + sub * 8;
    qa = *(const float4*)q;  qb = *(const float4*)(q + 4);
    ka = *(const float4*)kk; kb = *(const float4*)(kk + 4);
    float s = qa.x * ka.x + qa.y * ka.y + qa.z * ka.z + qa.w * ka.w
            + qb.x * kb.x + qb.y * kb.y + qb.z * kb.z + qb.w * kb.w;
    s += __shfl_xor_sync(0xffffffffu, s, 1);
    s += __shfl_xor_sync(0xffffffffu, s, 2);
    s += __shfl_xor_sync(0xffffffffu, s, 4);
    return s * C_BETA2;
}

__global__ void e2_fwd_kernel(const int* __restrict__ c2, const int* __restrict__ u2) {
    int e = blockIdx.x * 8 + (threadIdx.x >> 5);
    if (e >= NEDGE) return;
    int lane = threadIdx.x & 31;
    int h = lane >> 3, sub = lane & 7;
    int c = c2[e], u = u2[e];
    float4 qa, qb, ka, kb;
    float s = e2_dot(c, u, h, sub, qa, qb, ka, kb);
    if (sub == 0) atomicAdd(&g_Z2[c * HH + h], expf(s));
}

__global__ void e2_bwd_kernel(const int* __restrict__ c2, const int* __restrict__ u2) {
    int e = blockIdx.x * 8 + (threadIdx.x >> 5);
    if (e >= NEDGE) return;
    int lane = threadIdx.x & 31;
    int h = lane >> 3, sub = lane & 7;
    int c = c2[e], u = u2[e];
    float4 qa, qb, ka, kb;
    float s = e2_dot(c, u, h, sub, qa, qb, ka, kb);
    float z = g_Z2[c * HH + h];
    float w = -C_LAM2 * expf(s) / z;
    float* dq = g_dP + (size_t)c * PDIM + OQ2 + h * DZZ + sub * 8;
    float* dk = g_dP + (size_t)u * PDIM + OK2 + h * DZZ + sub * 8;
    atomicAdd(dq + 0, w * ka.x); atomicAdd(dq + 1, w * ka.y);
    atomicAdd(dq + 2, w * ka.z); atomicAdd(dq + 3, w * ka.w);
    atomicAdd(dq + 4, w * kb.x); atomicAdd(dq + 5, w * kb.y);
    atomicAdd(dq + 6, w * kb.z); atomicAdd(dq + 7, w * kb.w);
    atomicAdd(dk + 0, w * qa.x); atomicAdd(dk + 1, w * qa.y);
    atomicAdd(dk + 2, w * qa.z); atomicAdd(dk + 3, w * qa.w);
    atomicAdd(dk + 4, w * qb.x); atomicAdd(dk + 5, w * qb.y);
    atomicAdd(dk + 6, w * qb.z); atomicAdd(dk + 7, w * qb.w);
}

// ------------------- triple (3rd-order) motifs -------------------------------
__device__ __forceinline__ float e3_score(const float* __restrict__ T,
                                          int c, int u, int v, int m, int h, int sub) {
    size_t qb = (size_t)c * PDIM + OQ3 + h * 256 + sub * 32;
    size_t ub = (size_t)u * PDIM + OK3 + h * 256 + sub * 32;
    size_t vb = (size_t)v * PDIM + OK3 + h * 256 + sub * 32;
    const float* Tb = T + (size_t)m * (HH * RRR * DZZ) + h * 256 + sub * 32;
    float s = 0.f;
    #pragma unroll
    for (int j = 0; j < 32; j += 4) {
        float4 q = *(const float4*)(g_P + qb + j);
        float4 a = *(const float4*)(g_P + ub + j);
        float4 b = *(const float4*)(g_P + vb + j);
        float4 t = *(const float4*)(Tb + j);
        s += q.x * a.x * b.x * t.x + q.y * a.y * b.y * t.y
           + q.z * a.z * b.z * t.z + q.w * a.w * b.w * t.w;
    }
    s += __shfl_xor_sync(0xffffffffu, s, 1);
    s += __shfl_xor_sync(0xffffffffu, s, 2);
    s += __shfl_xor_sync(0xffffffffu, s, 4);
    return s * C_BETA3;
}

__global__ void e3_fwd_kernel(const int* __restrict__ c3, const int* __restrict__ u3,
                              const int* __restrict__ v3, const int* __restrict__ tt,
                              const float* __restrict__ T) {
    int t = blockIdx.x * 8 + (threadIdx.x >> 5);
    if (t >= NTRI) return;
    int lane = threadIdx.x & 31;
    int h = lane >> 3, sub = lane & 7;
    int c = c3[t], u = u3[t], v = v3[t], m = tt[t];
    float s = e3_score(T, c, u, v, m, h, sub);
    if (sub == 0) atomicAdd(&g_Z3[c * HH + h], expf(s));
}

__global__ void e3_bwd_kernel(const int* __restrict__ c3, const int* __restrict__ u3,
                              const int* __restrict__ v3, const int* __restrict__ tt,
                              const float* __restrict__ T) {
    int t = blockIdx.x * 8 + (threadIdx.x >> 5);
    if (t >= NTRI) return;
    int lane = threadIdx.x & 31;
    int h = lane >> 3, sub = lane & 7;
    int c = c3[t], u = u3[t], v = v3[t], m = tt[t];
    float s = e3_score(T, c, u, v, m, h, sub);
    float z = g_Z3[c * HH + h];
    float w = -C_LAM3 * expf(s) / z;
    size_t qb = (size_t)c * PDIM + OQ3 + h * 256 + sub * 32;
    size_t ub = (size_t)u * PDIM + OK3 + h * 256 + sub * 32;
    size_t vb = (size_t)v * PDIM + OK3 + h * 256 + sub * 32;
    const float* Tb = T + (size_t)m * (HH * RRR * DZZ) + h * 256 + sub * 32;
    #pragma unroll
    for (int j = 0; j < 32; j += 4) {
        float4 q = *(const float4*)(g_P + qb + j);
        float4 a = *(const float4*)(g_P + ub + j);
        float4 b = *(const float4*)(g_P + vb + j);
        float4 tv = *(const float4*)(Tb + j);
        atomicAdd(g_dP + qb + j + 0, w * a.x * b.x * tv.x);
        atomicAdd(g_dP + qb + j + 1, w * a.y * b.y * tv.y);
        atomicAdd(g_dP + qb + j + 2, w * a.z * b.z * tv.z);
        atomicAdd(g_dP + qb + j + 3, w * a.w * b.w * tv.w);
        atomicAdd(g_dP + ub + j + 0, w * q.x * b.x * tv.x);
        atomicAdd(g_dP + ub + j + 1, w * q.y * b.y * tv.y);
        atomicAdd(g_dP + ub + j + 2, w * q.z * b.z * tv.z);
        atomicAdd(g_dP + ub + j + 3, w * q.w * b.w * tv.w);
        atomicAdd(g_dP + vb + j + 0, w * q.x * a.x * tv.x);
        atomicAdd(g_dP + vb + j + 1, w * q.y * a.y * tv.y);
        atomicAdd(g_dP + vb + j + 2, w * q.x * a.y * tv.y * 0.f + w * q.y * a.z * 0.f + w * q.z * a.z * tv.z);
        atomicAdd(g_dP + vb + j + 3, w * q.w * a.w * tv.w);
    }
}

// ------------------- memory term (fused fwd + bwd) ---------------------------
__global__ void mem_kernel() {
    __shared__ float Ks[HH * DZZ * 33];
    __shared__ double eacc[8];
    for (int i = threadIdx.x; i < HH * DZZ * KMEM; i += 256) {
        int k = i & 31;
        int hz = i >> 5;
        Ks[hz * 33 + k] = g_Km[i];
    }
    __syncthreads();
    int w = threadIdx.x >> 5, lane = threadIdx.x & 31;
    int n = blockIdx.x * 8 + w;
    double lsum = 0.0;
    if (n < NNODE) {
        for (int h = 0; h < HH; h++) {
            size_t qoff = (size_t)n * PDIM + OQM + h * DZZ;
            float q0 = g_P[qoff + 2 * lane];
            float q1 = g_P[qoff + 2 * lane + 1];
            float acc = 0.f;
            #pragma unroll
            for (int zi = 0; zi < 32; zi++) {
                float qa = __shfl_sync(0xffffffffu, q0, zi);
                float qb = __shfl_sync(0xffffffffu, q1, zi);
                acc += qa * Ks[(h * DZZ + 2 * zi) * 33 + lane]
                     + qb * Ks[(h * DZZ + 2 * zi + 1) * 33 + lane];
            }
            float sm = C_BETAM * acc;
            float mx = sm;
            #pragma unroll
            for (int o = 16; o; o >>= 1) mx = fmaxf(mx, __shfl_xor_sync(0xffffffffu, mx, o));
            float ex = expf(sm - mx);
            float ssum = ex;
            #pragma unroll
            for (int o = 16; o; o >>= 1) ssum += __shfl_xor_sync(0xffffffffu, ssum, o);
            float lse = mx + logf(ssum);
            float p = ex / ssum;
            lsum += (double)lse;
            float d0 = 0.f, d1 = 0.f;
            #pragma unroll
            for (int k = 0; k < 32; k++) {
                float pk = __shfl_sync(0xffffffffu, p, k);
                d0 += pk * Ks[(h * DZZ + 2 * lane) * 33 + k];
                d1 += pk * Ks[(h * DZZ + 2 * lane + 1) * 33 + k];
            }
            g_dP[qoff + 2 * lane] = -C_LAMM * d0;
            g_dP[qoff + 2 * lane + 1] = -C_LAMM * d1;
        }
    }
    if (lane == 0) eacc[w] = -(double)C_LAMM * lsum;
    __syncthreads();
    if (threadIdx.x == 0) {
        double tot = 0.0;
        for (int i = 0; i < 8; i++) tot += eacc[i];
        atomicAdd(&g_E, tot);
    }
}

// ------------------- energy from segment sums --------------------------------
__global__ void lse_sum_kernel() {
    int i = blockIdx.x * 256 + threadIdx.x;
    double v = 0.0;
    if (i < NNODE * HH) {
        float z2 = g_Z2[i];
        if (z2 > 0.f) v -= (double)(C_LAM2 / C_BETA2) * (double)logf(z2);
        float z3 = g_Z3[i];
        if (z3 > 0.f) v -= (double)(C_LAM3 / C_BETA3) * (double)logf(z3);
    }
    #pragma unroll
    for (int o = 16; o; o >>= 1) v += __shfl_xor_sync(0xffffffffu, v, o);
    __shared__ double rd[8];
    if ((threadIdx.x & 31) == 0) rd[threadIdx.x >> 5] = v;
    __syncthreads();
    if (threadIdx.x == 0) {
        double t = 0.0;
        for (int j = 0; j < 8; j++) t += rd[j];
        atomicAdd(&g_E, t);
    }
}

// ------------------- LN backward + clip + step + clip (fused) ----------------
__global__ void ln_bwd_update_kernel(const float* __restrict__ X,
                                     const float* __restrict__ gamma,
                                     const float* __restrict__ step,
                                     float* __restrict__ out) {
    int n = blockIdx.x, d = threadIdx.x;
    size_t o = (size_t)n * DD + d;
    float dg = g_dG[o];
    float xh = g_xhat[o];
    float dxh = dg * gamma[d];
    float s1 = blk_sum256(dxh) * (1.0f / DD);
    float s2 = blk_sum256(dxh * xh) * (1.0f / DD);
    float dx = g_rstd[n] * (dxh - s1 - xh * s2);
    float gn2 = blk_sum256(dx * dx);
    float gn = sqrtf(gn2);
    float sc = C_GCLIP / fmaxf(gn, C_GCLIP);
    float xn = X[o] - step[0] * C_DAMP * dx * sc;
    float sn2 = blk_sum256(xn * xn);
    float sn = sqrtf(sn2);
    float sc2 = C_SCLIP / fmaxf(sn, C_SCLIP);
    out[o] = xn * sc2;
}

__global__ void finalize_kernel(float* __restrict__ out, int out_size) {
    if (out_size > NNODE * DD) out[(size_t)NNODE * DD] = (float)g_E;
}

// ------------------- launch --------------------------------------------------
extern "C" void kernel_launch(void* const* d_in, const int* in_sizes, int n_in,
                              void* d_out, int out_size) {
    const float* X     = (const float*)d_in[0];
    const int*   c2    = (const int*)d_in[1];
    const int*   u2    = (const int*)d_in[2];
    const int*   c3    = (const int*)d_in[3];
    const int*   u3    = (const int*)d_in[4];
    const int*   v3    = (const int*)d_in[5];
    const int*   tt    = (const int*)d_in[6];
    // d_in[7] = batch (unused)
    const float* step  = (const float*)d_in[8];
    const float* gamma = (const float*)d_in[9];
    const float* bias  = (const float*)d_in[10];
    const float* wq2   = (const float*)d_in[11];
    const float* wk2   = (const float*)d_in[12];
    const float* wq3   = (const float*)d_in[13];
    const float* wk3   = (const float*)d_in[14];
    const float* T     = (const float*)d_in[15];
    const float* wqm   = (const float*)d_in[16];
    const float* wkm   = (const float*)d_in[17];
    const float* bmem  = (const float*)d_in[18];
    float* out = (float*)d_out;

    cudaFuncSetAttribute(gemm_mma_kernel, cudaFuncAttributeMaxDynamicSharedMemorySize, GSMEM);

    zero_dP_kernel<<<4096, 256>>>();
    zero_small_kernel<<<(NNODE * HH + 255) / 256, 256>>>();
    ln_fwd_kernel<<<NNODE, 256>>>(X, gamma, bias);
    pack_w_kernel<<<(PDIM * DD + 255) / 256, 256>>>(wq2, wk2, wq3, wk3, wqm);
    km_kernel<<<(HH * DZZ * KMEM + 255) / 256, 256>>>(bmem, wkm);

    // forward GEMM: P = G * Wcat^T  (HMMA; bf16x3 only for Q2/K2 col tiles)
    gemm_mma_kernel<<<dim3(PDIM / TBN, NPAD / TBM), 256, GSMEM>>>(0);

    e2_fwd_kernel<<<NEDGE / 8, 256>>>(c2, u2);
    e3_fwd_kernel<<<NTRI / 8, 256>>>(c3, u3, v3, tt, T);
    mem_kernel<<<(NNODE + 7) / 8, 256>>>();
    lse_sum_kernel<<<(NNODE * HH + 255) / 256, 256>>>();

    e2_bwd_kernel<<<NEDGE / 8, 256>>>(c2, u2);
    e3_bwd_kernel<<<NTRI / 8, 256>>>(c3, u3, v3, tt, T);

    conv_dP_kernel<<<4096, 256>>>();
    // backward GEMM: dG = dP * Wcat  (HMMA, single bf16 pass)
    gemm_mma_kernel<<<dim3(DD / TBN, NPAD / TBM), 256, GSMEM>>>(1);

    ln_bwd_update_kernel<<<NNODE, 256>>>(X, gamma, step, out);
    finalize_kernel<<<1, 1>>>(out, out_size);
}

// round 15
// speedup vs baseline: 2.7412x; 1.9804x over previous
#include <cuda_runtime.h>
#include <cuda_bf16.h>
#include <math.h>
#include <stdint.h>

#define NNODE 50000
#define NPAD 50048            // 391*128, padded row count for MMA tiles
#define DD 256
#define HH 4
#define DZZ 64
#define RRR 4
#define KMEM 32
#define MMOT 2
#define NEDGE 1600000
#define NTRI 100000
#define PDIM 2816
#define OQ2 0
#define OK2 256
#define OQ3 512
#define OK3 1536
#define OQM 2560
#define C_LAM2 1.0f
#define C_LAM3 0.5f
#define C_LAMM 1.0f
#define C_BETA2 1.0f
#define C_BETA3 1.0f
#define C_BETAM 1.0f
#define C_GCLIP 1.0f
#define C_SCLIP 10.0f
#define C_DAMP 0.9999f
#define C_EPS 1e-5f

// ------------------- scratch (static device globals; no allocs) -------------
__device__ float g_xhat[(size_t)NNODE * DD];
__device__ float g_rstd[NNODE];
__device__ float g_P[(size_t)NNODE * PDIM];    // packed projections [n][2816]
__device__ float g_dP[(size_t)NNODE * PDIM];   // packed projection grads
__device__ float g_dG[(size_t)NNODE * DD];
__device__ float g_Z2[NNODE * HH];
__device__ float g_Z3[NNODE * HH];
__device__ float g_Km[HH * DZZ * KMEM];        // memory keys [h][z][k]
__device__ double g_E;
// bf16 operands for HMMA GEMMs (padded rows stay zero-initialized)
__device__ __nv_bfloat16 g_Ghi[(size_t)NPAD * DD];
__device__ __nv_bfloat16 g_Glo[(size_t)NPAD * DD];
__device__ __nv_bfloat16 g_Whi[(size_t)PDIM * DD];
__device__ __nv_bfloat16 g_Wlo[(size_t)PDIM * DD];
__device__ __nv_bfloat16 g_WThi[(size_t)DD * PDIM];
__device__ __nv_bfloat16 g_dPhi[(size_t)NPAD * PDIM];

// ------------------- PTX helpers (plain sm_103-safe) -------------------------
__device__ __forceinline__ uint32_t smem_u32(const void* p) {
    uint32_t a;
    asm("{ .reg .u64 t; cvta.to.shared.u64 t, %1; cvt.u32.u64 %0, t; }"
        : "=r"(a) : "l"(p));
    return a;
}
__device__ __forceinline__ void cp16(uint32_t dst, const void* src) {
    asm volatile("cp.async.cg.shared.global [%0], [%1], 16;" :: "r"(dst), "l"(src));
}
#define CP_COMMIT() asm volatile("cp.async.commit_group;" ::: "memory")
#define CP_WAIT1()  asm volatile("cp.async.wait_group 1;" ::: "memory")
__device__ __forceinline__ void ldmx4(uint32_t* r, uint32_t addr) {
    asm volatile("ldmatrix.sync.aligned.m8n8.x4.shared.b16 {%0,%1,%2,%3}, [%4];"
                 : "=r"(r[0]), "=r"(r[1]), "=r"(r[2]), "=r"(r[3]) : "r"(addr));
}
__device__ __forceinline__ void mma16816(float* c, const uint32_t* a,
                                         uint32_t b0, uint32_t b1) {
    asm volatile("mma.sync.aligned.m16n8k16.row.col.f32.bf16.bf16.f32 "
                 "{%0,%1,%2,%3}, {%4,%5,%6,%7}, {%8,%9}, {%0,%1,%2,%3};"
                 : "+f"(c[0]), "+f"(c[1]), "+f"(c[2]), "+f"(c[3])
                 : "r"(a[0]), "r"(a[1]), "r"(a[2]), "r"(a[3]), "r"(b0), "r"(b1));
}
__device__ __forceinline__ uint32_t swz128(uint32_t b) { return b ^ ((b >> 3) & 0x70); }
// vectorized global float reduction (sm_90+ baseline, 4x fewer atomic ops)
__device__ __forceinline__ void red4(float* addr, float a, float b, float c, float d) {
    asm volatile("red.global.add.v4.f32 [%0], {%1, %2, %3, %4};"
                 :: "l"(addr), "f"(a), "f"(b), "f"(c), "f"(d) : "memory");
}

// ------------------- block reduce helper ------------------------------------
__device__ __forceinline__ float blk_sum256(float v) {
    __shared__ float red[8];
    #pragma unroll
    for (int o = 16; o; o >>= 1) v += __shfl_xor_sync(0xffffffffu, v, o);
    if ((threadIdx.x & 31) == 0) red[threadIdx.x >> 5] = v;
    __syncthreads();
    float r;
    if (threadIdx.x < 32) {
        float t = (threadIdx.x < 8) ? red[threadIdx.x] : 0.0f;
        #pragma unroll
        for (int o = 4; o; o >>= 1) t += __shfl_xor_sync(0xffffffffu, t, o);
        if (threadIdx.x == 0) red[0] = t;
    }
    __syncthreads();
    r = red[0];
    __syncthreads();
    return r;
}

// ------------------- zero kernels -------------------------------------------
__global__ void zero_dP_kernel() {
    size_t i = (size_t)blockIdx.x * blockDim.x + threadIdx.x;
    size_t n4 = (size_t)NNODE * PDIM / 4;
    float4 z = make_float4(0.f, 0.f, 0.f, 0.f);
    for (; i < n4; i += (size_t)gridDim.x * blockDim.x)
        ((float4*)g_dP)[i] = z;
}
__global__ void zero_small_kernel() {
    int i = blockIdx.x * blockDim.x + threadIdx.x;
    if (i < NNODE * HH) { g_Z2[i] = 0.f; g_Z3[i] = 0.f; }
    if (i == 0) g_E = 0.0;
}

// ------------------- LayerNorm forward (+ bf16 hi/lo split of G) ------------
__global__ void ln_fwd_kernel(const float* __restrict__ X,
                              const float* __restrict__ gamma,
                              const float* __restrict__ bias) {
    int n = blockIdx.x, d = threadIdx.x;
    size_t o = (size_t)n * DD + d;
    float x = X[o];
    float mu = blk_sum256(x) * (1.0f / DD);
    float dv = x - mu;
    float var = blk_sum256(dv * dv) * (1.0f / DD);
    float rstd = rsqrtf(var + C_EPS);
    float xh = dv * rstd;
    g_xhat[o] = xh;
    float gv = gamma[d] * xh + bias[d];
    __nv_bfloat16 hi = __float2bfloat16(gv);
    g_Ghi[o] = hi;
    g_Glo[o] = __float2bfloat16(gv - __bfloat162float(hi));
    if (d == 0) g_rstd[n] = rstd;
}

// ------------------- weight packing (+ split + transpose) -------------------
__global__ void pack_w_kernel(const float* __restrict__ wq2, const float* __restrict__ wk2,
                              const float* __restrict__ wq3, const float* __restrict__ wk3,
                              const float* __restrict__ wqm) {
    int i = blockIdx.x * blockDim.x + threadIdx.x;
    if (i >= PDIM * DD) return;
    int p = i / DD, d = i % DD;
    float v;
    if (p < 256)       v = wq2[i];
    else if (p < 512)  v = wk2[i - 256 * DD];
    else if (p < 1536) v = wq3[i - 512 * DD];
    else if (p < 2560) v = wk3[i - 1536 * DD];
    else               v = wqm[i - 2560 * DD];
    __nv_bfloat16 hi = __float2bfloat16(v);
    g_Whi[i] = hi;
    g_Wlo[i] = __float2bfloat16(v - __bfloat162float(hi));
    g_WThi[(size_t)d * PDIM + p] = hi;
}

// Km[h][z][k] = sum_d B_mem[k,d] * W_Km[h,z,d]
__global__ void km_kernel(const float* __restrict__ Bm, const float* __restrict__ Wkm) {
    int i = blockIdx.x * blockDim.x + threadIdx.x;
    if (i >= HH * DZZ * KMEM) return;
    int k = i % KMEM;
    int hz = i / KMEM;
    const float* b = Bm + (size_t)k * DD;
    const float* w = Wkm + (size_t)hz * DD;
    float acc = 0.f;
    #pragma unroll 8
    for (int d = 0; d < DD; d++) acc += b[d] * w[d];
    g_Km[i] = acc;
}

// ------------------- convert dP to bf16 (hi only; bwd tolerates bf16) --------
__global__ void conv_dP_kernel() {
    size_t i = (size_t)blockIdx.x * blockDim.x + threadIdx.x;
    size_t n4 = (size_t)NNODE * PDIM / 4;
    __nv_bfloat162* ph = (__nv_bfloat162*)g_dPhi;
    for (; i < n4; i += (size_t)gridDim.x * blockDim.x) {
        float4 v = ((const float4*)g_dP)[i];
        ph[2 * i]     = __nv_bfloat162(__float2bfloat16(v.x), __float2bfloat16(v.y));
        ph[2 * i + 1] = __nv_bfloat162(__float2bfloat16(v.z), __float2bfloat16(v.w));
    }
}

// ------------------- HMMA GEMM (mma.sync bf16, cp.async pipelined) -----------
// C[M][N] = A[M][K] * B[N][K]^T  (both K-major)
// mode 0: P = G * Wcat^T. N-tiles 0-3 (Q2/K2 cols) use bf16x3 split
//         (12 chunks: hi*hi, hi*lo, lo*hi over K=256); other tiles 4 chunks hi*hi.
// mode 1: dG = dPhi * WThi^T-style (single bf16 pass, K=2816, 44 chunks).
#define TBM 128
#define TBN 128
#define TBK 64
#define TILEB 16384                    // one operand tile: 128 rows x 128B
#define STAGEB (2 * TILEB)
#define GSMEM (3 * STAGEB)             // 3 stages

__global__ __launch_bounds__(256, 1) void gemm_mma_kernel(int mode) {
    extern __shared__ char sm[];
    const uint32_t su = smem_u32(sm);
    const int tid = threadIdx.x, wid = tid >> 5, lane = tid & 31;
    const int m0 = blockIdx.y * TBM;
    const int n0 = blockIdx.x * TBN;
    const int wm = wid & 3, wn = wid >> 2;    // 4 M-warps x 2 N-warps

    int lda, ldb, ldc, nchunk;
    float* C;
    if (mode == 0) {
        lda = DD; ldb = DD; ldc = PDIM; C = g_P;
        nchunk = (n0 < 512) ? 12 : 4;
    } else {
        lda = PDIM; ldb = PDIM; ldc = DD; C = g_dG;
        nchunk = PDIM / TBK;              // 44
    }

    auto prefetch = [&](int c, int st) {
        const __nv_bfloat16 *Asrc, *Bsrc;
        int k0;
        if (mode == 0) {
            int pass = c >> 2;
            k0 = (c & 3) * TBK;
            Asrc = (pass < 2) ? g_Ghi : g_Glo;
            Bsrc = (pass == 1) ? g_Wlo : g_Whi;
        } else {
            k0 = c * TBK;
            Asrc = g_dPhi;
            Bsrc = g_WThi;
        }
        uint32_t bufA = su + st * STAGEB;
        uint32_t bufB = bufA + TILEB;
        #pragma unroll
        for (int g = 0; g < 4; g++) {
            int i = tid + g * 256;            // 0..1023
            int row = i >> 3;
            int c8 = (i & 7) * 8;
            uint32_t off = swz128((uint32_t)(row * 128 + (i & 7) * 16));
            cp16(bufA + off, Asrc + (size_t)(m0 + row) * lda + k0 + c8);
            cp16(bufB + off, Bsrc + (size_t)(n0 + row) * ldb + k0 + c8);
        }
    };

    float acc[2][8][4] = {};

    prefetch(0, 0); CP_COMMIT();
    prefetch(1, 1); CP_COMMIT();

    for (int c = 0; c < nchunk; c++) {
        const int st = c % 3;
        CP_WAIT1();
        __syncthreads();
        if (c + 2 < nchunk) prefetch(c + 2, (c + 2) % 3);
        CP_COMMIT();

        const uint32_t aBase = su + st * STAGEB;
        const uint32_t bBase = aBase + TILEB;
        #pragma unroll
        for (int kk = 0; kk < 4; kk++) {
            uint32_t ra[2][4];
            #pragma unroll
            for (int im = 0; im < 2; im++) {
                int r = wm * 32 + im * 16 + (lane & 15);
                uint32_t byte = (uint32_t)(r * 128 + kk * 32 + ((lane >> 4) * 16));
                ldmx4(ra[im], aBase + swz128(byte));
            }
            uint32_t rb[4][4];
            #pragma unroll
            for (int jb = 0; jb < 4; jb++) {
                int r = wn * 64 + jb * 16 + (lane & 7) + ((lane >> 4) * 8);
                uint32_t byte = (uint32_t)(r * 128 + kk * 32 + (((lane >> 3) & 1) * 16));
                ldmx4(rb[jb], bBase + swz128(byte));
            }
            #pragma unroll
            for (int im = 0; im < 2; im++)
                #pragma unroll
                for (int jb = 0; jb < 4; jb++) {
                    mma16816(acc[im][jb * 2],     ra[im], rb[jb][0], rb[jb][1]);
                    mma16816(acc[im][jb * 2 + 1], ra[im], rb[jb][2], rb[jb][3]);
                }
        }
    }

    // epilogue: C fragment lane layout: rows l/4 and l/4+8, cols (l%4)*2,+1
    #pragma unroll
    for (int im = 0; im < 2; im++)
        #pragma unroll
        for (int jn = 0; jn < 8; jn++) {
            float* cc = acc[im][jn];
            int m = m0 + wm * 32 + im * 16 + (lane >> 2);
            int col = n0 + wn * 64 + jn * 8 + (lane & 3) * 2;
            if (m < NNODE)
                *(float2*)(C + (size_t)m * ldc + col) = make_float2(cc[0], cc[1]);
            if (m + 8 < NNODE)
                *(float2*)(C + (size_t)(m + 8) * ldc + col) = make_float2(cc[2], cc[3]);
        }
}

// ------------------- pair (2nd-order) edges ---------------------------------
__device__ __forceinline__ float e2_dot(int c, int u, int h, int sub,
                                        float4& qa, float4& qb, float4& ka, float4& kb) {
    const float* q = g_P + (size_t)c * PDIM + OQ2 + h * DZZ + sub * 8;
    const float* kk = g_P + (size_t)u * PDIM + OK2 + h * DZZ + sub * 8;
    qa = *(const float4*)q;  qb = *(const float4*)(q + 4);
    ka = *(const float4*)kk; kb = *(const float4*)(kk + 4);
    float s = qa.x * ka.x + qa.y * ka.y + qa.z * ka.z + qa.w * ka.w
            + qb.x * kb.x + qb.y * kb.y + qb.z * kb.z + qb.w * kb.w;
    s += __shfl_xor_sync(0xffffffffu, s, 1);
    s += __shfl_xor_sync(0xffffffffu, s, 2);
    s += __shfl_xor_sync(0xffffffffu, s, 4);
    return s * C_BETA2;
}

__global__ void e2_fwd_kernel(const int* __restrict__ c2, const int* __restrict__ u2) {
    int e = blockIdx.x * 8 + (threadIdx.x >> 5);
    if (e >= NEDGE) return;
    int lane = threadIdx.x & 31;
    int h = lane >> 3, sub = lane & 7;
    int c = c2[e], u = u2[e];
    float4 qa, qb, ka, kb;
    float s = e2_dot(c, u, h, sub, qa, qb, ka, kb);
    if (sub == 0) atomicAdd(&g_Z2[c * HH + h], expf(s));
}

__global__ void e2_bwd_kernel(const int* __restrict__ c2, const int* __restrict__ u2) {
    int e = blockIdx.x * 8 + (threadIdx.x >> 5);
    if (e >= NEDGE) return;
    int lane = threadIdx.x & 31;
    int h = lane >> 3, sub = lane & 7;
    int c = c2[e], u = u2[e];
    float4 qa, qb, ka, kb;
    float s = e2_dot(c, u, h, sub, qa, qb, ka, kb);
    float z = g_Z2[c * HH + h];
    float w = -C_LAM2 * expf(s) / z;
    float* dq = g_dP + (size_t)c * PDIM + OQ2 + h * DZZ + sub * 8;
    float* dk = g_dP + (size_t)u * PDIM + OK2 + h * DZZ + sub * 8;
    red4(dq,     w * ka.x, w * ka.y, w * ka.z, w * ka.w);
    red4(dq + 4, w * kb.x, w * kb.y, w * kb.z, w * kb.w);
    red4(dk,     w * qa.x, w * qa.y, w * qa.z, w * qa.w);
    red4(dk + 4, w * qb.x, w * qb.y, w * qb.z, w * qb.w);
}

// ------------------- triple (3rd-order) motifs -------------------------------
__device__ __forceinline__ float e3_score(const float* __restrict__ T,
                                          int c, int u, int v, int m, int h, int sub) {
    size_t qb = (size_t)c * PDIM + OQ3 + h * 256 + sub * 32;
    size_t ub = (size_t)u * PDIM + OK3 + h * 256 + sub * 32;
    size_t vb = (size_t)v * PDIM + OK3 + h * 256 + sub * 32;
    const float* Tb = T + (size_t)m * (HH * RRR * DZZ) + h * 256 + sub * 32;
    float s = 0.f;
    #pragma unroll
    for (int j = 0; j < 32; j += 4) {
        float4 q = *(const float4*)(g_P + qb + j);
        float4 a = *(const float4*)(g_P + ub + j);
        float4 b = *(const float4*)(g_P + vb + j);
        float4 t = *(const float4*)(Tb + j);
        s += q.x * a.x * b.x * t.x + q.y * a.y * b.y * t.y
           + q.z * a.z * b.z * t.z + q.w * a.w * b.w * t.w;
    }
    s += __shfl_xor_sync(0xffffffffu, s, 1);
    s += __shfl_xor_sync(0xffffffffu, s, 2);
    s += __shfl_xor_sync(0xffffffffu, s, 4);
    return s * C_BETA3;
}

__global__ void e3_fwd_kernel(const int* __restrict__ c3, const int* __restrict__ u3,
                              const int* __restrict__ v3, const int* __restrict__ tt,
                              const float* __restrict__ T) {
    int t = blockIdx.x * 8 + (threadIdx.x >> 5);
    if (t >= NTRI) return;
    int lane = threadIdx.x & 31;
    int h = lane >> 3, sub = lane & 7;
    int c = c3[t], u = u3[t], v = v3[t], m = tt[t];
    float s = e3_score(T, c, u, v, m, h, sub);
    if (sub == 0) atomicAdd(&g_Z3[c * HH + h], expf(s));
}

__global__ void e3_bwd_kernel(const int* __restrict__ c3, const int* __restrict__ u3,
                              const int* __restrict__ v3, const int* __restrict__ tt,
                              const float* __restrict__ T) {
    int t = blockIdx.x * 8 + (threadIdx.x >> 5);
    if (t >= NTRI) return;
    int lane = threadIdx.x & 31;
    int h = lane >> 3, sub = lane & 7;
    int c = c3[t], u = u3[t], v = v3[t], m = tt[t];
    float s = e3_score(T, c, u, v, m, h, sub);
    float z = g_Z3[c * HH + h];
    float w = -C_LAM3 * expf(s) / z;
    size_t qb = (size_t)c * PDIM + OQ3 + h * 256 + sub * 32;
    size_t ub = (size_t)u * PDIM + OK3 + h * 256 + sub * 32;
    size_t vb = (size_t)v * PDIM + OK3 + h * 256 + sub * 32;
    const float* Tb = T + (size_t)m * (HH * RRR * DZZ) + h * 256 + sub * 32;
    #pragma unroll
    for (int j = 0; j < 32; j += 4) {
        float4 q = *(const float4*)(g_P + qb + j);
        float4 a = *(const float4*)(g_P + ub + j);
        float4 b = *(const float4*)(g_P + vb + j);
        float4 tv = *(const float4*)(Tb + j);
        red4(g_dP + qb + j, w * a.x * b.x * tv.x, w * a.y * b.y * tv.y,
                            w * a.z * b.z * tv.z, w * a.w * b.w * tv.w);
        red4(g_dP + ub + j, w * q.x * b.x * tv.x, w * q.y * b.y * tv.y,
                            w * q.z * b.z * tv.z, w * q.w * b.w * tv.w);
        red4(g_dP + vb + j, w * q.x * a.x * tv.x, w * q.y * a.y * tv.y,
                            w * q.z * a.z * tv.z, w * q.w * a.w * tv.w);
    }
}

// ------------------- memory term (fused fwd + bwd) ---------------------------
__global__ void mem_kernel() {
    __shared__ float Ks[HH * DZZ * 33];
    __shared__ double eacc[8];
    for (int i = threadIdx.x; i < HH * DZZ * KMEM; i += 256) {
        int k = i & 31;
        int hz = i >> 5;
        Ks[hz * 33 + k] = g_Km[i];
    }
    __syncthreads();
    int w = threadIdx.x >> 5, lane = threadIdx.x & 31;
    int n = blockIdx.x * 8 + w;
    double lsum = 0.0;
    if (n < NNODE) {
        for (int h = 0; h < HH; h++) {
            size_t qoff = (size_t)n * PDIM + OQM + h * DZZ;
            float q0 = g_P[qoff + 2 * lane];
            float q1 = g_P[qoff + 2 * lane + 1];
            float acc = 0.f;
            #pragma unroll
            for (int zi = 0; zi < 32; zi++) {
                float qa = __shfl_sync(0xffffffffu, q0, zi);
                float qb = __shfl_sync(0xffffffffu, q1, zi);
                acc += qa * Ks[(h * DZZ + 2 * zi) * 33 + lane]
                     + qb * Ks[(h * DZZ + 2 * zi + 1) * 33 + lane];
            }
            float sm = C_BETAM * acc;
            float mx = sm;
            #pragma unroll
            for (int o = 16; o; o >>= 1) mx = fmaxf(mx, __shfl_xor_sync(0xffffffffu, mx, o));
            float ex = expf(sm - mx);
            float ssum = ex;
            #pragma unroll
            for (int o = 16; o; o >>= 1) ssum += __shfl_xor_sync(0xffffffffu, ssum, o);
            float lse = mx + logf(ssum);
            float p = ex / ssum;
            lsum += (double)lse;
            float d0 = 0.f, d1 = 0.f;
            #pragma unroll
            for (int k = 0; k < 32; k++) {
                float pk = __shfl_sync(0xffffffffu, p, k);
                d0 += pk * Ks[(h * DZZ + 2 * lane) * 33 + k];
                d1 += pk * Ks[(h * DZZ + 2 * lane + 1) * 33 + k];
            }
            g_dP[qoff + 2 * lane] = -C_LAMM * d0;
            g_dP[qoff + 2 * lane + 1] = -C_LAMM * d1;
        }
    }
    if (lane == 0) eacc[w] = -(double)C_LAMM * lsum;
    __syncthreads();
    if (threadIdx.x == 0) {
        double tot = 0.0;
        for (int i = 0; i < 8; i++) tot += eacc[i];
        atomicAdd(&g_E, tot);
    }
}

// ------------------- energy from segment sums --------------------------------
__global__ void lse_sum_kernel() {
    int i = blockIdx.x * 256 + threadIdx.x;
    double v = 0.0;
    if (i < NNODE * HH) {
        float z2 = g_Z2[i];
        if (z2 > 0.f) v -= (double)(C_LAM2 / C_BETA2) * (double)logf(z2);
        float z3 = g_Z3[i];
        if (z3 > 0.f) v -= (double)(C_LAM3 / C_BETA3) * (double)logf(z3);
    }
    #pragma unroll
    for (int o = 16; o; o >>= 1) v += __shfl_xor_sync(0xffffffffu, v, o);
    __shared__ double rd[8];
    if ((threadIdx.x & 31) == 0) rd[threadIdx.x >> 5] = v;
    __syncthreads();
    if (threadIdx.x == 0) {
        double t = 0.0;
        for (int j = 0; j < 8; j++) t += rd[j];
        atomicAdd(&g_E, t);
    }
}

// ------------------- LN backward + clip + step + clip (fused) ----------------
__global__ void ln_bwd_update_kernel(const float* __restrict__ X,
                                     const float* __restrict__ gamma,
                                     const float* __restrict__ step,
                                     float* __restrict__ out) {
    int n = blockIdx.x, d = threadIdx.x;
    size_t o = (size_t)n * DD + d;
    float dg = g_dG[o];
    float xh = g_xhat[o];
    float dxh = dg * gamma[d];
    float s1 = blk_sum256(dxh) * (1.0f / DD);
    float s2 = blk_sum256(dxh * xh) * (1.0f / DD);
    float dx = g_rstd[n] * (dxh - s1 - xh * s2);
    float gn2 = blk_sum256(dx * dx);
    float gn = sqrtf(gn2);
    float sc = C_GCLIP / fmaxf(gn, C_GCLIP);
    float xn = X[o] - step[0] * C_DAMP * dx * sc;
    float sn2 = blk_sum256(xn * xn);
    float sn = sqrtf(sn2);
    float sc2 = C_SCLIP / fmaxf(sn, C_SCLIP);
    out[o] = xn * sc2;
}

__global__ void finalize_kernel(float* __restrict__ out, int out_size) {
    if (out_size > NNODE * DD) out[(size_t)NNODE * DD] = (float)g_E;
}

// ------------------- launch --------------------------------------------------
extern "C" void kernel_launch(void* const* d_in, const int* in_sizes, int n_in,
                              void* d_out, int out_size) {
    const float* X     = (const float*)d_in[0];
    const int*   c2    = (const int*)d_in[1];
    const int*   u2    = (const int*)d_in[2];
    const int*   c3    = (const int*)d_in[3];
    const int*   u3    = (const int*)d_in[4];
    const int*   v3    = (const int*)d_in[5];
    const int*   tt    = (const int*)d_in[6];
    // d_in[7] = batch (unused)
    const float* step  = (const float*)d_in[8];
    const float* gamma = (const float*)d_in[9];
    const float* bias  = (const float*)d_in[10];
    const float* wq2   = (const float*)d_in[11];
    const float* wk2   = (const float*)d_in[12];
    const float* wq3   = (const float*)d_in[13];
    const float* wk3   = (const float*)d_in[14];
    const float* T     = (const float*)d_in[15];
    const float* wqm   = (const float*)d_in[16];
    const float* wkm   = (const float*)d_in[17];
    const float* bmem  = (const float*)d_in[18];
    float* out = (float*)d_out;

    cudaFuncSetAttribute(gemm_mma_kernel, cudaFuncAttributeMaxDynamicSharedMemorySize, GSMEM);

    zero_dP_kernel<<<4096, 256>>>();
    zero_small_kernel<<<(NNODE * HH + 255) / 256, 256>>>();
    ln_fwd_kernel<<<NNODE, 256>>>(X, gamma, bias);
    pack_w_kernel<<<(PDIM * DD + 255) / 256, 256>>>(wq2, wk2, wq3, wk3, wqm);
    km_kernel<<<(HH * DZZ * KMEM + 255) / 256, 256>>>(bmem, wkm);

    // forward GEMM: P = G * Wcat^T  (HMMA; bf16x3 only for Q2/K2 col tiles)
    gemm_mma_kernel<<<dim3(PDIM / TBN, NPAD / TBM), 256, GSMEM>>>(0);

    e2_fwd_kernel<<<NEDGE / 8, 256>>>(c2, u2);
    e3_fwd_kernel<<<NTRI / 8, 256>>>(c3, u3, v3, tt, T);
    mem_kernel<<<(NNODE + 7) / 8, 256>>>();
    lse_sum_kernel<<<(NNODE * HH + 255) / 256, 256>>>();

    e2_bwd_kernel<<<NEDGE / 8, 256>>>(c2, u2);
    e3_bwd_kernel<<<NTRI / 8, 256>>>(c3, u3, v3, tt, T);

    conv_dP_kernel<<<4096, 256>>>();
    // backward GEMM: dG = dP * Wcat  (HMMA, single bf16 pass)
    gemm_mma_kernel<<<dim3(DD / TBN, NPAD / TBM), 256, GSMEM>>>(1);

    ln_bwd_update_kernel<<<NNODE, 256>>>(X, gamma, step, out);
    finalize_kernel<<<1, 1>>>(out, out_size);
}